// round 1
// baseline (speedup 1.0000x reference)
#include <cuda_runtime.h>
#include <math.h>

#define BB 8
#define NSEQ 1024
#define CDIM 768
#define NH 12
#define HD 64
#define SCALE 0.125f
#define BNEPS 1e-5f
#define OUT_OFF (BB*NSEQ*CDIM)   /* 6,291,456 floats: 'out' first, then 'attn' */

// ---------------- scratch (device globals; no allocations allowed) ----------
__device__ float  g_q[BB*NH*NSEQ*HD];          // scaled by SCALE
__device__ float  g_k[BB*NH*NSEQ*HD];
__device__ float  g_v[BB*NH*NSEQ*HD];
__device__ float  g_logits[BB*NH*NSEQ*NSEQ];   // 402 MB
__device__ float  g_rmax[BB*NH*NSEQ];
__device__ float  g_rsinv[BB*NH*NSEQ];
__device__ double g_s1[NH];
__device__ double g_s2[NH];
__device__ float  g_bna[NH];
__device__ float  g_bnc[NH];
__device__ float  g_t[BB*NSEQ*CDIM];           // attn@v in (B,N,C) layout

// ---------------- init BN accumulators --------------------------------------
__global__ void k_init() {
    int t = threadIdx.x;
    if (t < NH) { g_s1[t] = 0.0; g_s2[t] = 0.0; }
}

// ---------------- K1: QKV GEMM (NT) + bias + scatter -------------------------
// X[8192,768] @ Wqkv[2304,768]^T ; 64x64 tile, 256 thr, 4x4/thread, k-step 16
__global__ void k_qkv(const float* __restrict__ x, const float* __restrict__ w,
                      const float* __restrict__ bias) {
    __shared__ __align__(16) float As[16][68];
    __shared__ __align__(16) float Bs[16][68];
    const int j0 = blockIdx.x * 64;          // 0..2240
    const int m0 = blockIdx.y * 64;          // 0..8128
    const int tid = threadIdx.x;
    const int tx = tid & 15, ty = tid >> 4;
    const int lr = tid >> 2;                 // 0..63
    const int lc = (tid & 3) << 2;           // 0,4,8,12
    float acc[4][4] = {};
    for (int k0 = 0; k0 < CDIM; k0 += 16) {
        float4 av = *(const float4*)(x + (size_t)(m0 + lr) * CDIM + k0 + lc);
        float4 bv = *(const float4*)(w + (size_t)(j0 + lr) * CDIM + k0 + lc);
        As[lc+0][lr]=av.x; As[lc+1][lr]=av.y; As[lc+2][lr]=av.z; As[lc+3][lr]=av.w;
        Bs[lc+0][lr]=bv.x; Bs[lc+1][lr]=bv.y; Bs[lc+2][lr]=bv.z; Bs[lc+3][lr]=bv.w;
        __syncthreads();
        #pragma unroll
        for (int kk = 0; kk < 16; kk++) {
            float4 a = *(const float4*)&As[kk][ty << 2];
            float4 b = *(const float4*)&Bs[kk][tx << 2];
            acc[0][0]+=a.x*b.x; acc[0][1]+=a.x*b.y; acc[0][2]+=a.x*b.z; acc[0][3]+=a.x*b.w;
            acc[1][0]+=a.y*b.x; acc[1][1]+=a.y*b.y; acc[1][2]+=a.y*b.z; acc[1][3]+=a.y*b.w;
            acc[2][0]+=a.z*b.x; acc[2][1]+=a.z*b.y; acc[2][2]+=a.z*b.z; acc[2][3]+=a.z*b.w;
            acc[3][0]+=a.w*b.x; acc[3][1]+=a.w*b.y; acc[3][2]+=a.w*b.z; acc[3][3]+=a.w*b.w;
        }
        __syncthreads();
    }
    const int t3 = j0 / CDIM;                // 0:q 1:k 2:v (tile never crosses)
    const int h  = (j0 % CDIM) >> 6;
    float* dst = (t3 == 0) ? g_q : (t3 == 1) ? g_k : g_v;
    const float sc = (t3 == 0) ? SCALE : 1.0f;
    #pragma unroll
    for (int i = 0; i < 4; i++) {
        int m = m0 + (ty << 2) + i;
        int b = m >> 10, n = m & (NSEQ - 1);
        float* row = dst + (((size_t)(b * NH + h)) * NSEQ + n) * HD + (tx << 2);
        int jb = j0 + (tx << 2);
        float4 st;
        st.x = (acc[i][0] + bias[jb+0]) * sc;
        st.y = (acc[i][1] + bias[jb+1]) * sc;
        st.z = (acc[i][2] + bias[jb+2]) * sc;
        st.w = (acc[i][3] + bias[jb+3]) * sc;
        *(float4*)row = st;
    }
}

// ---------------- K2: logits = q @ k^T (per b,h) -----------------------------
__global__ void k_qk() {
    __shared__ __align__(16) float As[16][68];
    __shared__ __align__(16) float Bs[16][68];
    const int m0 = blockIdx.x * 64;          // key tile
    const int n0 = blockIdx.y * 64;          // query tile
    const int bh = blockIdx.z;               // 0..95
    const float* qb = g_q + (size_t)bh * NSEQ * HD;
    const float* kb = g_k + (size_t)bh * NSEQ * HD;
    const int tid = threadIdx.x;
    const int tx = tid & 15, ty = tid >> 4;
    const int lr = tid >> 2;
    const int lc = (tid & 3) << 2;
    float acc[4][4] = {};
    for (int k0 = 0; k0 < HD; k0 += 16) {
        float4 av = *(const float4*)(qb + (size_t)(n0 + lr) * HD + k0 + lc);
        float4 bv = *(const float4*)(kb + (size_t)(m0 + lr) * HD + k0 + lc);
        As[lc+0][lr]=av.x; As[lc+1][lr]=av.y; As[lc+2][lr]=av.z; As[lc+3][lr]=av.w;
        Bs[lc+0][lr]=bv.x; Bs[lc+1][lr]=bv.y; Bs[lc+2][lr]=bv.z; Bs[lc+3][lr]=bv.w;
        __syncthreads();
        #pragma unroll
        for (int kk = 0; kk < 16; kk++) {
            float4 a = *(const float4*)&As[kk][ty << 2];
            float4 b = *(const float4*)&Bs[kk][tx << 2];
            acc[0][0]+=a.x*b.x; acc[0][1]+=a.x*b.y; acc[0][2]+=a.x*b.z; acc[0][3]+=a.x*b.w;
            acc[1][0]+=a.y*b.x; acc[1][1]+=a.y*b.y; acc[1][2]+=a.y*b.z; acc[1][3]+=a.y*b.w;
            acc[2][0]+=a.z*b.x; acc[2][1]+=a.z*b.y; acc[2][2]+=a.z*b.z; acc[2][3]+=a.z*b.w;
            acc[3][0]+=a.w*b.x; acc[3][1]+=a.w*b.y; acc[3][2]+=a.w*b.z; acc[3][3]+=a.w*b.w;
        }
        __syncthreads();
    }
    float* out = g_logits + (size_t)bh * NSEQ * NSEQ;
    #pragma unroll
    for (int i = 0; i < 4; i++) {
        int n = n0 + (ty << 2) + i;
        float4 st = {acc[i][0], acc[i][1], acc[i][2], acc[i][3]};
        *(float4*)(out + (size_t)n * NSEQ + m0 + (tx << 2)) = st;
    }
}

// ---------------- K3: per-row max + inv(sum exp) (warp per row) -------------
__global__ void k_rowstat() {
    int warp = (blockIdx.x * blockDim.x + threadIdx.x) >> 5;
    int lane = threadIdx.x & 31;
    if (warp >= BB * NH * NSEQ) return;
    const float* row = g_logits + (size_t)warp * NSEQ;
    float4 v[8];
    float mx = -1e30f;
    #pragma unroll
    for (int i = 0; i < 8; i++) {
        v[i] = *(const float4*)(row + (((i << 5) + lane) << 2));
        mx = fmaxf(mx, fmaxf(fmaxf(v[i].x, v[i].y), fmaxf(v[i].z, v[i].w)));
    }
    #pragma unroll
    for (int o = 16; o; o >>= 1) mx = fmaxf(mx, __shfl_xor_sync(0xffffffffu, mx, o));
    float s = 0.f;
    #pragma unroll
    for (int i = 0; i < 8; i++) {
        s += __expf(v[i].x - mx) + __expf(v[i].y - mx)
           + __expf(v[i].z - mx) + __expf(v[i].w - mx);
    }
    #pragma unroll
    for (int o = 16; o; o >>= 1) s += __shfl_xor_sync(0xffffffffu, s, o);
    if (lane == 0) { g_rmax[warp] = mx; g_rsinv[warp] = 1.0f / s; }
}

// ---------------- K4: softmax + 12x12 head mix + BN stats --------------------
// one block per (b,n); thread t owns float4 of m = 4t; writes raw mixed to d_out
__global__ void k_mix(const float* __restrict__ w_re, const float* __restrict__ b_re,
                      float* __restrict__ dout) {
    __shared__ float wre[NH][NH];
    __shared__ float bre[NH], rm[NH], rs[NH];
    __shared__ float sm1[NH], sm2[NH];
    const int b = blockIdx.x >> 10;
    const int n = blockIdx.x & 1023;
    const int t = threadIdx.x;               // 256
    if (t < NH * NH) wre[t / NH][t % NH] = w_re[t];
    if (t < NH) {
        bre[t] = b_re[t];
        int r = (b * NH + t) * NSEQ + n;
        rm[t] = g_rmax[r]; rs[t] = g_rsinv[r];
        sm1[t] = 0.f; sm2[t] = 0.f;
    }
    __syncthreads();
    const int m = t << 2;
    float p[NH][4];
    #pragma unroll
    for (int h = 0; h < NH; h++) {
        const float4 L = *(const float4*)(g_logits +
            (((size_t)(b * NH + h)) * NSEQ + n) * NSEQ + m);
        p[h][0] = __expf(L.x - rm[h]) * rs[h];
        p[h][1] = __expf(L.y - rm[h]) * rs[h];
        p[h][2] = __expf(L.z - rm[h]) * rs[h];
        p[h][3] = __expf(L.w - rm[h]) * rs[h];
    }
    float* attn = dout + OUT_OFF;
    float ls1[NH], ls2[NH];
    #pragma unroll
    for (int g = 0; g < NH; g++) {
        float o0 = bre[g], o1 = bre[g], o2 = bre[g], o3 = bre[g];
        #pragma unroll
        for (int h = 0; h < NH; h++) {
            float wgh = wre[g][h];
            o0 += wgh * p[h][0]; o1 += wgh * p[h][1];
            o2 += wgh * p[h][2]; o3 += wgh * p[h][3];
        }
        float4 st = {o0, o1, o2, o3};
        *(float4*)(attn + (((size_t)(b * NH + g)) * NSEQ + n) * NSEQ + m) = st;
        ls1[g] = o0 + o1 + o2 + o3;
        ls2[g] = o0*o0 + o1*o1 + o2*o2 + o3*o3;
    }
    #pragma unroll
    for (int g = 0; g < NH; g++) {
        float a = ls1[g], c = ls2[g];
        #pragma unroll
        for (int o = 16; o; o >>= 1) {
            a += __shfl_xor_sync(0xffffffffu, a, o);
            c += __shfl_xor_sync(0xffffffffu, c, o);
        }
        if ((t & 31) == 0) { atomicAdd(&sm1[g], a); atomicAdd(&sm2[g], c); }
    }
    __syncthreads();
    if (t < NH) {
        atomicAdd(&g_s1[t], (double)sm1[t]);
        atomicAdd(&g_s2[t], (double)sm2[t]);
    }
}

// ---------------- K5: BN finalize (double precision) -------------------------
__global__ void k_bnfin(const float* __restrict__ gamma, const float* __restrict__ beta) {
    int g = threadIdx.x;
    if (g < NH) {
        double cnt = (double)BB * NSEQ * NSEQ;
        double mean = g_s1[g] / cnt;
        double var  = g_s2[g] / cnt - mean * mean;
        float a = (float)((double)gamma[g] / sqrt(var + (double)BNEPS));
        g_bna[g] = a;
        g_bnc[g] = beta[g] - a * (float)mean;
    }
}

// ---------------- K6: in-place affine normalize of attn ----------------------
__global__ void k_norm(float* __restrict__ dout) {
    size_t i4 = (size_t)blockIdx.x * blockDim.x + threadIdx.x;   // float4 idx
    int g = (int)((i4 >> 18) % NH);          // 1024*1024/4 = 2^18 per (b,g)
    float a = g_bna[g], c = g_bnc[g];
    float4* p = (float4*)( (char*)dout + (size_t)OUT_OFF * 4 ) + i4;
    float4 v = *p;
    v.x = v.x * a + c; v.y = v.y * a + c; v.z = v.z * a + c; v.w = v.w * a + c;
    *p = v;
}

// ---------------- K7: out_head = attn_norm @ v (per b,g) ---------------------
__global__ void k_av(const float* __restrict__ attn) {
    __shared__ __align__(16) float As[16][68];
    __shared__ __align__(16) float Bs[16][68];
    const int n0 = blockIdx.x * 64;
    const int bg = blockIdx.y;               // 0..95
    const int b = bg / NH, g = bg % NH;
    const float* A = attn + (size_t)bg * NSEQ * NSEQ;
    const float* V = g_v  + (size_t)bg * NSEQ * HD;
    const int tid = threadIdx.x;
    const int tx = tid & 15, ty = tid >> 4;
    const int lr = tid >> 2;
    const int lc = (tid & 3) << 2;
    const int bk = tid >> 4;                 // kk row of V tile
    const int bd = (tid & 15) << 2;          // d offset
    float acc[4][4] = {};
    for (int m0 = 0; m0 < NSEQ; m0 += 16) {
        float4 av = *(const float4*)(A + (size_t)(n0 + lr) * NSEQ + m0 + lc);
        As[lc+0][lr]=av.x; As[lc+1][lr]=av.y; As[lc+2][lr]=av.z; As[lc+3][lr]=av.w;
        float4 bv = *(const float4*)(V + (size_t)(m0 + bk) * HD + bd);
        *(float4*)&Bs[bk][bd] = bv;
        __syncthreads();
        #pragma unroll
        for (int kk = 0; kk < 16; kk++) {
            float4 a = *(const float4*)&As[kk][ty << 2];
            float4 bq = *(const float4*)&Bs[kk][tx << 2];
            acc[0][0]+=a.x*bq.x; acc[0][1]+=a.x*bq.y; acc[0][2]+=a.x*bq.z; acc[0][3]+=a.x*bq.w;
            acc[1][0]+=a.y*bq.x; acc[1][1]+=a.y*bq.y; acc[1][2]+=a.y*bq.z; acc[1][3]+=a.y*bq.w;
            acc[2][0]+=a.z*bq.x; acc[2][1]+=a.z*bq.y; acc[2][2]+=a.z*bq.z; acc[2][3]+=a.z*bq.w;
            acc[3][0]+=a.w*bq.x; acc[3][1]+=a.w*bq.y; acc[3][2]+=a.w*bq.z; acc[3][3]+=a.w*bq.w;
        }
        __syncthreads();
    }
    #pragma unroll
    for (int i = 0; i < 4; i++) {
        int n = n0 + (ty << 2) + i;
        float4 st = {acc[i][0], acc[i][1], acc[i][2], acc[i][3]};
        *(float4*)(g_t + ((size_t)(b * NSEQ + n)) * CDIM + g * HD + (tx << 2)) = st;
    }
}

// ---------------- K8: final projection (NT) + bias ---------------------------
__global__ void k_proj(const float* __restrict__ wp, const float* __restrict__ bp,
                       float* __restrict__ dout) {
    __shared__ __align__(16) float As[16][68];
    __shared__ __align__(16) float Bs[16][68];
    const int j0 = blockIdx.x * 64;          // 0..704
    const int m0 = blockIdx.y * 64;
    const int tid = threadIdx.x;
    const int tx = tid & 15, ty = tid >> 4;
    const int lr = tid >> 2;
    const int lc = (tid & 3) << 2;
    float acc[4][4] = {};
    for (int k0 = 0; k0 < CDIM; k0 += 16) {
        float4 av = *(const float4*)(g_t + (size_t)(m0 + lr) * CDIM + k0 + lc);
        float4 bv = *(const float4*)(wp  + (size_t)(j0 + lr) * CDIM + k0 + lc);
        As[lc+0][lr]=av.x; As[lc+1][lr]=av.y; As[lc+2][lr]=av.z; As[lc+3][lr]=av.w;
        Bs[lc+0][lr]=bv.x; Bs[lc+1][lr]=bv.y; Bs[lc+2][lr]=bv.z; Bs[lc+3][lr]=bv.w;
        __syncthreads();
        #pragma unroll
        for (int kk = 0; kk < 16; kk++) {
            float4 a = *(const float4*)&As[kk][ty << 2];
            float4 b = *(const float4*)&Bs[kk][tx << 2];
            acc[0][0]+=a.x*b.x; acc[0][1]+=a.x*b.y; acc[0][2]+=a.x*b.z; acc[0][3]+=a.x*b.w;
            acc[1][0]+=a.y*b.x; acc[1][1]+=a.y*b.y; acc[1][2]+=a.y*b.z; acc[1][3]+=a.y*b.w;
            acc[2][0]+=a.z*b.x; acc[2][1]+=a.z*b.y; acc[2][2]+=a.z*b.z; acc[2][3]+=a.z*b.w;
            acc[3][0]+=a.w*b.x; acc[3][1]+=a.w*b.y; acc[3][2]+=a.w*b.z; acc[3][3]+=a.w*b.w;
        }
        __syncthreads();
    }
    #pragma unroll
    for (int i = 0; i < 4; i++) {
        int m = m0 + (ty << 2) + i;
        int jb = j0 + (tx << 2);
        float4 st;
        st.x = acc[i][0] + bp[jb+0];
        st.y = acc[i][1] + bp[jb+1];
        st.z = acc[i][2] + bp[jb+2];
        st.w = acc[i][3] + bp[jb+3];
        *(float4*)(dout + (size_t)m * CDIM + jb) = st;
    }
}

// ---------------- launcher ----------------------------------------------------
extern "C" void kernel_launch(void* const* d_in, const int* in_sizes, int n_in,
                              void* d_out, int out_size) {
    const float* x    = (const float*)d_in[0];
    const float* wqkv = (const float*)d_in[1];
    const float* bqkv = (const float*)d_in[2];
    const float* wre  = (const float*)d_in[3];
    const float* bre  = (const float*)d_in[4];
    const float* gam  = (const float*)d_in[5];
    const float* bet  = (const float*)d_in[6];
    const float* wp   = (const float*)d_in[7];
    const float* bp   = (const float*)d_in[8];
    float* out = (float*)d_out;

    k_init<<<1, 32>>>();
    k_qkv<<<dim3(36, 128), 256>>>(x, wqkv, bqkv);
    k_qk<<<dim3(16, 16, 96), 256>>>();
    k_rowstat<<<12288, 256>>>();
    k_mix<<<8192, 256>>>(wre, bre, out);
    k_bnfin<<<1, 32>>>(gam, bet);
    k_norm<<<98304, 256>>>(out);
    k_av<<<dim3(16, 96), 256>>>(out + OUT_OFF);
    k_proj<<<dim3(12, 128), 256>>>(wp, bp, out);
}

// round 2
// speedup vs baseline: 1.4633x; 1.4633x over previous
#include <cuda_runtime.h>
#include <math.h>
#include <stdint.h>

#define BB 8
#define NSEQ 1024
#define CDIM 768
#define NH 12
#define HD 64
#define SCALE 0.125f
#define BNEPS 1e-5f
#define OUT_OFF (BB*NSEQ*CDIM)
#define NN ((size_t)NSEQ*NSEQ)

// ---------------- scratch (device globals) -----------------------------------
__device__ float  g_q[BB*NH*NSEQ*HD];          // scaled by SCALE
__device__ float  g_k[BB*NH*NSEQ*HD];
__device__ float  g_vt[BB*NH*HD*NSEQ];         // transposed: [bh][d][m]
__device__ float  g_logits[BB*NH*NSEQ*NSEQ];   // 402 MB
__device__ double g_s1[NH];
__device__ double g_s2[NH];
__device__ float  g_bna[NH];
__device__ float  g_bnc[NH];
__device__ float  g_t[BB*NSEQ*CDIM];           // attn@v in (B,N,C) layout

// ---------------- helpers -----------------------------------------------------
__device__ __forceinline__ uint32_t f2tf(float x){
    uint32_t r; asm("cvt.rna.tf32.f32 %0, %1;" : "=r"(r) : "f"(x)); return r;
}
__device__ __forceinline__ void mma8(float* c, const uint32_t* a, const uint32_t* b){
    asm volatile("mma.sync.aligned.m16n8k8.row.col.f32.tf32.tf32.f32 "
        "{%0,%1,%2,%3}, {%4,%5,%6,%7}, {%8,%9}, {%0,%1,%2,%3};"
        : "+f"(c[0]), "+f"(c[1]), "+f"(c[2]), "+f"(c[3])
        : "r"(a[0]), "r"(a[1]), "r"(a[2]), "r"(a[3]), "r"(b[0]), "r"(b[1]));
}

__global__ void k_init(){ int t = threadIdx.x; if (t < NH){ g_s1[t]=0.0; g_s2[t]=0.0; } }

// ---------------- unified tf32x3 GEMM: C[M,N] = A[M,K] * B[N,K]^T -------------
// MODE 0: qkv   A=x[8192,768]      B=w_qkv[2304,768]  -> scatter q/k/vt (+bias, q*SCALE)
// MODE 1: qk    A=g_q[bh]          B=g_k[bh]  K=64    -> g_logits[bh]
// MODE 2: av    A=attn[bh] (raw!)  B=g_vt[bh] K=1024  -> g_t ; normalizes A on load + writeback
// MODE 3: proj  A=g_t[8192,768]    B=w_proj[768,768]  -> d_out (+bias)
template<int BN, int MODE>
__global__ __launch_bounds__(256, 2) void gemm_k(
    const float* __restrict__ pA, const float* __restrict__ pB,
    const float* __restrict__ bias, float* __restrict__ pC)
{
    constexpr int BM = 128, BK = 16, LDK = 20;
    constexpr int NT = (BN/2)/8, MT = 2;
    constexpr int K     = (MODE==1) ? 64 : (MODE==2) ? 1024 : 768;
    constexpr int LDA_G = (MODE==1) ? 64 : (MODE==2) ? 1024 : 768;
    constexpr int LDB_G = (MODE==1) ? 64 : (MODE==2) ? 1024 : 768;

    __shared__ __align__(16) uint32_t Ah[BM][LDK], Al[BM][LDK];
    __shared__ __align__(16) uint32_t Bh[BN][LDK], Bl[BN][LDK];

    const int tid  = threadIdx.x;
    const int lane = tid & 31, warp = tid >> 5;
    const int wm = warp >> 1, wn = warp & 1;          // 4 x 2 warp grid
    const int gid = lane >> 2, tig = lane & 3;
    const int Mblk = blockIdx.y * BM;
    const int Nblk = blockIdx.x * BN;
    const int bh   = blockIdx.z;

    const float* Asrc; const float* Bsrc;
    if constexpr (MODE == 0)      { Asrc = pA; Bsrc = pB; }
    else if constexpr (MODE == 1) { Asrc = g_q + (size_t)bh*NSEQ*HD; Bsrc = g_k + (size_t)bh*NSEQ*HD; }
    else if constexpr (MODE == 2) { Asrc = pA + (size_t)bh*NN; Bsrc = g_vt + (size_t)bh*HD*NSEQ; }
    else                          { Asrc = g_t; Bsrc = pB; }

    float na = 0.f, nc = 0.f;
    if constexpr (MODE == 2) { int g = bh % NH; na = g_bna[g]; nc = g_bnc[g]; }

    const int ar = tid >> 2;            // 0..63
    const int ac = (tid & 3) << 2;      // 0,4,8,12
    const float* agp0 = Asrc + (size_t)(Mblk + ar) * LDA_G + ac;
    const float* agp1 = agp0 + (size_t)64 * LDA_G;
    const float* bgp0 = Bsrc + (size_t)(Nblk + ar) * LDB_G + ac;
    const float* bgp1 = bgp0 + (size_t)64 * LDB_G;   // only used when BN==128

    float4 ra0, ra1, rb0, rb1;
    ra0 = *(const float4*)agp0;
    ra1 = *(const float4*)agp1;
    rb0 = *(const float4*)bgp0;
    if constexpr (BN == 128) rb1 = *(const float4*)bgp1;

    float acc[MT][NT][4] = {};

    for (int k0 = 0; k0 < K; k0 += BK) {
        // normalize + writeback (AV mode): each attn element touched exactly once
        if constexpr (MODE == 2) {
            ra0.x = fmaf(na, ra0.x, nc); ra0.y = fmaf(na, ra0.y, nc);
            ra0.z = fmaf(na, ra0.z, nc); ra0.w = fmaf(na, ra0.w, nc);
            ra1.x = fmaf(na, ra1.x, nc); ra1.y = fmaf(na, ra1.y, nc);
            ra1.z = fmaf(na, ra1.z, nc); ra1.w = fmaf(na, ra1.w, nc);
            *(float4*)((float*)(agp0 + k0)) = ra0;
            *(float4*)((float*)(agp1 + k0)) = ra1;
        }
        // split into tf32 hi/lo and store to smem ([row][k], LDK=20)
        {
            uint4 h, l;
            h.x=f2tf(ra0.x); l.x=f2tf(ra0.x-__uint_as_float(h.x));
            h.y=f2tf(ra0.y); l.y=f2tf(ra0.y-__uint_as_float(h.y));
            h.z=f2tf(ra0.z); l.z=f2tf(ra0.z-__uint_as_float(h.z));
            h.w=f2tf(ra0.w); l.w=f2tf(ra0.w-__uint_as_float(h.w));
            *(uint4*)&Ah[ar][ac] = h; *(uint4*)&Al[ar][ac] = l;
            h.x=f2tf(ra1.x); l.x=f2tf(ra1.x-__uint_as_float(h.x));
            h.y=f2tf(ra1.y); l.y=f2tf(ra1.y-__uint_as_float(h.y));
            h.z=f2tf(ra1.z); l.z=f2tf(ra1.z-__uint_as_float(h.z));
            h.w=f2tf(ra1.w); l.w=f2tf(ra1.w-__uint_as_float(h.w));
            *(uint4*)&Ah[ar+64][ac] = h; *(uint4*)&Al[ar+64][ac] = l;
            h.x=f2tf(rb0.x); l.x=f2tf(rb0.x-__uint_as_float(h.x));
            h.y=f2tf(rb0.y); l.y=f2tf(rb0.y-__uint_as_float(h.y));
            h.z=f2tf(rb0.z); l.z=f2tf(rb0.z-__uint_as_float(h.z));
            h.w=f2tf(rb0.w); l.w=f2tf(rb0.w-__uint_as_float(h.w));
            *(uint4*)&Bh[ar][ac] = h; *(uint4*)&Bl[ar][ac] = l;
            if constexpr (BN == 128) {
                h.x=f2tf(rb1.x); l.x=f2tf(rb1.x-__uint_as_float(h.x));
                h.y=f2tf(rb1.y); l.y=f2tf(rb1.y-__uint_as_float(h.y));
                h.z=f2tf(rb1.z); l.z=f2tf(rb1.z-__uint_as_float(h.z));
                h.w=f2tf(rb1.w); l.w=f2tf(rb1.w-__uint_as_float(h.w));
                *(uint4*)&Bh[ar+64][ac] = h; *(uint4*)&Bl[ar+64][ac] = l;
            }
        }
        __syncthreads();
        // prefetch next tile (overlaps with MMA below)
        if (k0 + BK < K) {
            ra0 = *(const float4*)(agp0 + k0 + BK);
            ra1 = *(const float4*)(agp1 + k0 + BK);
            rb0 = *(const float4*)(bgp0 + k0 + BK);
            if constexpr (BN == 128) rb1 = *(const float4*)(bgp1 + k0 + BK);
        }
        #pragma unroll
        for (int ks = 0; ks < BK; ks += 8) {
            uint32_t afh[MT][4], afl[MT][4];
            #pragma unroll
            for (int i = 0; i < MT; i++) {
                int mb = wm*32 + i*16 + gid;
                afh[i][0]=Ah[mb  ][ks+tig  ]; afl[i][0]=Al[mb  ][ks+tig  ];
                afh[i][1]=Ah[mb+8][ks+tig  ]; afl[i][1]=Al[mb+8][ks+tig  ];
                afh[i][2]=Ah[mb  ][ks+tig+4]; afl[i][2]=Al[mb  ][ks+tig+4];
                afh[i][3]=Ah[mb+8][ks+tig+4]; afl[i][3]=Al[mb+8][ks+tig+4];
            }
            #pragma unroll
            for (int j = 0; j < NT; j++) {
                int nb = wn*(BN/2) + j*8 + gid;
                uint32_t bh2[2], bl2[2];
                bh2[0]=Bh[nb][ks+tig]; bh2[1]=Bh[nb][ks+tig+4];
                bl2[0]=Bl[nb][ks+tig]; bl2[1]=Bl[nb][ks+tig+4];
                #pragma unroll
                for (int i = 0; i < MT; i++) {
                    mma8(acc[i][j], afh[i], bh2);
                    mma8(acc[i][j], afl[i], bh2);
                    mma8(acc[i][j], afh[i], bl2);
                }
            }
        }
        __syncthreads();
    }

    // ----------------- epilogue -----------------
    #pragma unroll
    for (int i = 0; i < MT; i++) {
        #pragma unroll
        for (int j = 0; j < NT; j++) {
            const float* c = acc[i][j];
            int r0 = Mblk + wm*32 + i*16 + gid;
            int c0 = Nblk + wn*(BN/2) + j*8 + tig*2;
            #pragma unroll
            for (int p = 0; p < 2; p++) {
                int row = r0 + p*8;
                float v0 = c[p*2+0], v1 = c[p*2+1];
                if constexpr (MODE == 0) {
                    int t3 = c0 / CDIM; int rem = c0 - t3*CDIM;
                    int h = rem >> 6, d = rem & 63;
                    int b = row >> 10, n = row & (NSEQ-1);
                    float b0 = bias[c0], b1 = bias[c0+1];
                    if (t3 == 0) {
                        float2 s = make_float2((v0+b0)*SCALE, (v1+b1)*SCALE);
                        *(float2*)(g_q + ((((size_t)(b*NH+h))*NSEQ + n)<<6) + d) = s;
                    } else if (t3 == 1) {
                        float2 s = make_float2(v0+b0, v1+b1);
                        *(float2*)(g_k + ((((size_t)(b*NH+h))*NSEQ + n)<<6) + d) = s;
                    } else {
                        size_t base = (((size_t)(b*NH+h))*HD + d)*NSEQ + n;
                        g_vt[base]        = v0+b0;
                        g_vt[base + NSEQ] = v1+b1;
                    }
                } else if constexpr (MODE == 1) {
                    float2 s = make_float2(v0, v1);
                    *(float2*)(g_logits + (size_t)bh*NN + (size_t)row*NSEQ + c0) = s;
                } else if constexpr (MODE == 2) {
                    int b = bh / NH, g = bh % NH;
                    float2 s = make_float2(v0, v1);
                    *(float2*)(g_t + ((size_t)b*NSEQ + row)*CDIM + g*HD + c0) = s;
                } else {
                    float2 s = make_float2(v0 + bias[c0], v1 + bias[c0+1]);
                    *(float2*)(pC + (size_t)row*CDIM + c0) = s;
                }
            }
        }
    }
}

// ---------------- fused softmax + 12x12 head mix + BN stats ------------------
// one block per (b,n); thread t owns the float4 at m = 4t; writes RAW mixed attn
__global__ void k_mix(const float* __restrict__ w_re, const float* __restrict__ b_re,
                      float* __restrict__ dout) {
    __shared__ float wre[NH][NH];
    __shared__ float bre[NH], smax[NH], sinv[NH];
    __shared__ float red[NH][8];
    __shared__ float sm1[NH], sm2[NH];
    const int b = blockIdx.x >> 10;
    const int n = blockIdx.x & 1023;
    const int t = threadIdx.x;               // 256
    const int lane = t & 31, warp = t >> 5;
    if (t < NH*NH) wre[t/NH][t%NH] = w_re[t];
    if (t < NH) { bre[t] = b_re[t]; sm1[t]=0.f; sm2[t]=0.f; }
    const int m = t << 2;
    float L[NH][4];
    #pragma unroll
    for (int h = 0; h < NH; h++) {
        float4 v = *(const float4*)(g_logits + (((size_t)(b*NH+h))*NSEQ + n)*NSEQ + m);
        L[h][0]=v.x; L[h][1]=v.y; L[h][2]=v.z; L[h][3]=v.w;
        float mx = fmaxf(fmaxf(v.x, v.y), fmaxf(v.z, v.w));
        #pragma unroll
        for (int o = 16; o; o >>= 1) mx = fmaxf(mx, __shfl_xor_sync(0xffffffffu, mx, o));
        if (lane == 0) red[h][warp] = mx;
    }
    __syncthreads();
    if (t < NH) {
        float mx = red[t][0];
        #pragma unroll
        for (int w = 1; w < 8; w++) mx = fmaxf(mx, red[t][w]);
        smax[t] = mx;
    }
    __syncthreads();
    #pragma unroll
    for (int h = 0; h < NH; h++) {
        float mh = smax[h];
        L[h][0]=__expf(L[h][0]-mh); L[h][1]=__expf(L[h][1]-mh);
        L[h][2]=__expf(L[h][2]-mh); L[h][3]=__expf(L[h][3]-mh);
        float s = (L[h][0]+L[h][1]) + (L[h][2]+L[h][3]);
        #pragma unroll
        for (int o = 16; o; o >>= 1) s += __shfl_xor_sync(0xffffffffu, s, o);
        if (lane == 0) red[h][warp] = s;
    }
    __syncthreads();
    if (t < NH) {
        float s = 0.f;
        #pragma unroll
        for (int w = 0; w < 8; w++) s += red[t][w];
        sinv[t] = 1.0f / s;
    }
    __syncthreads();
    #pragma unroll
    for (int h = 0; h < NH; h++) {
        float si = sinv[h];
        L[h][0]*=si; L[h][1]*=si; L[h][2]*=si; L[h][3]*=si;
    }
    float* attn = dout + OUT_OFF;
    #pragma unroll
    for (int g = 0; g < NH; g++) {
        float o0=bre[g], o1=bre[g], o2=bre[g], o3=bre[g];
        #pragma unroll
        for (int h = 0; h < NH; h++) {
            float w = wre[g][h];
            o0 = fmaf(w, L[h][0], o0); o1 = fmaf(w, L[h][1], o1);
            o2 = fmaf(w, L[h][2], o2); o3 = fmaf(w, L[h][3], o3);
        }
        float4 st = {o0, o1, o2, o3};
        *(float4*)(attn + (((size_t)(b*NH+g))*NSEQ + n)*NSEQ + m) = st;
        float a = (o0+o1)+(o2+o3);
        float c = o0*o0+o1*o1+o2*o2+o3*o3;
        #pragma unroll
        for (int o = 16; o; o >>= 1) {
            a += __shfl_xor_sync(0xffffffffu, a, o);
            c += __shfl_xor_sync(0xffffffffu, c, o);
        }
        if (lane == 0) { atomicAdd(&sm1[g], a); atomicAdd(&sm2[g], c); }
    }
    __syncthreads();
    if (t < NH) {
        atomicAdd(&g_s1[t], (double)sm1[t]);
        atomicAdd(&g_s2[t], (double)sm2[t]);
    }
}

// ---------------- BN finalize (double precision) -----------------------------
__global__ void k_bnfin(const float* __restrict__ gamma, const float* __restrict__ beta) {
    int g = threadIdx.x;
    if (g < NH) {
        double cnt = (double)BB * NSEQ * NSEQ;
        double mean = g_s1[g] / cnt;
        double var  = g_s2[g] / cnt - mean * mean;
        float a = (float)((double)gamma[g] / sqrt(var + (double)BNEPS));
        g_bna[g] = a;
        g_bnc[g] = beta[g] - a * (float)mean;
    }
}

// ---------------- launcher ----------------------------------------------------
extern "C" void kernel_launch(void* const* d_in, const int* in_sizes, int n_in,
                              void* d_out, int out_size) {
    const float* x    = (const float*)d_in[0];
    const float* wqkv = (const float*)d_in[1];
    const float* bqkv = (const float*)d_in[2];
    const float* wre  = (const float*)d_in[3];
    const float* bre  = (const float*)d_in[4];
    const float* gam  = (const float*)d_in[5];
    const float* bet  = (const float*)d_in[6];
    const float* wp   = (const float*)d_in[7];
    const float* bp   = (const float*)d_in[8];
    float* out = (float*)d_out;

    k_init<<<1, 32>>>();
    gemm_k<128,0><<<dim3(18, 64, 1), 256>>>(x, wqkv, bqkv, nullptr);       // qkv
    gemm_k<128,1><<<dim3(8, 8, 96), 256>>>(nullptr, nullptr, nullptr, nullptr); // qk
    k_mix<<<8192, 256>>>(wre, bre, out);
    k_bnfin<<<1, 32>>>(gam, bet);
    gemm_k<64,2><<<dim3(1, 8, 96), 256>>>(out + OUT_OFF, nullptr, nullptr, nullptr); // av + norm
    gemm_k<128,3><<<dim3(6, 64, 1), 256>>>(nullptr, wp, bp, out);          // proj
}